// round 4
// baseline (speedup 1.0000x reference)
#include <cuda_runtime.h>
#include <cstdint>

// SNNController: T=1000, B=8192, I=9, H=96, O=3
// out[0 : T*B*O) = spk2_rec, out[T*B*O : 2*T*B*O) = mem2_rec
//
// R3: weights W1/W2 moved to SMEM (one copy per CTA, packed f32x2 pairs,
// read via LDS.128). Registers drop ~220 -> ~110, enabling 2 CTAs/SM via
// __launch_bounds__(256,2): all 256 CTAs resident in ONE wave, 16 warps/SM.
// fma-pipe-bound model: ~672 cyc/SM/step -> ~380-450us.

#define T_STEPS 1000
#define BATCH   8192
#define NIN     9
#define NH      96
#define NO      3
#define GSZ     8
#define HPL     12
#define JP      6     // f32x2 pairs per lane
#define NPAIR   (NH/2)   // 48 pairs total

using ull = unsigned long long;

__device__ __forceinline__ ull pk2(float lo, float hi) {
    ull r; asm("mov.b64 %0, {%1, %2};" : "=l"(r) : "f"(lo), "f"(hi)); return r;
}
__device__ __forceinline__ float2 upk2(ull v) {
    float2 r; asm("mov.b64 {%0, %1}, %2;" : "=f"(r.x), "=f"(r.y) : "l"(v)); return r;
}
__device__ __forceinline__ ull ffma2(ull a, ull b, ull c) {
    ull d; asm("fma.rn.f32x2 %0, %1, %2, %3;" : "=l"(d) : "l"(a), "l"(b), "l"(c)); return d;
}
__device__ __forceinline__ float fsetgt(float a, float b) {
    float r; asm("set.gt.f32.f32 %0, %1, %2;" : "=f"(r) : "f"(a), "f"(b)); return r;
}

__global__ void __launch_bounds__(256, 2)
snn_kernel(const float* __restrict__ x,
           const float* __restrict__ W1, const float* __restrict__ b1,
           const float* __restrict__ W2, const float* __restrict__ b2,
           float* __restrict__ out)
{
    // Packed weights in smem, shared by all 32 batch-groups of the CTA.
    // w1s[i][p] = (W1[2p][i], W1[2p+1][i])   -- transposed + h-paired
    // w2s[o][p] = (W2[o][2p], W2[o][2p+1])
    __shared__ ull w1s[NIN][NPAIR];
    __shared__ ull w2s[NO][NPAIR];

    for (int idx = threadIdx.x; idx < NIN * NPAIR; idx += blockDim.x) {
        const int i = idx / NPAIR, p = idx % NPAIR, h = 2 * p;
        w1s[i][p] = pk2(W1[h * NIN + i], W1[(h + 1) * NIN + i]);
    }
    for (int idx = threadIdx.x; idx < NO * NPAIR; idx += blockDim.x) {
        const int o = idx / NPAIR, p = idx % NPAIR;
        w2s[o][p] = pk2(W2[o * NH + 2 * p], W2[o * NH + 2 * p + 1]);
    }
    __syncthreads();

    const int tid = blockIdx.x * blockDim.x + threadIdx.x;
    const int b   = tid >> 3;     // batch element
    const int s   = tid & 7;      // sublane in group
    const int h0  = s * HPL;

    // per-lane biases in registers (small)
    ull b1p[JP];
#pragma unroll
    for (int j = 0; j < JP; j++)
        b1p[j] = pk2(b1[h0 + 2 * j], b1[h0 + 2 * j + 1]);
    const float b20 = b2[0], b21 = b2[1], b22 = b2[2];

    // lane's weight slices (16B-aligned: s*6 pairs * 8B = 48B, multiple of 16)
    const ulonglong2* w1l[NIN];
#pragma unroll
    for (int i = 0; i < NIN; i++)
        w1l[i] = (const ulonglong2*)&w1s[i][s * JP];
    const ulonglong2* w2l0 = (const ulonglong2*)&w2s[0][s * JP];
    const ulonglong2* w2l1 = (const ulonglong2*)&w2s[1][s * JP];
    const ulonglong2* w2l2 = (const ulonglong2*)&w2s[2][s * JP];

    // state
    ull m1[JP], s1[JP];
#pragma unroll
    for (int j = 0; j < JP; j++) { m1[j] = 0ull; s1[j] = 0ull; }
    float mem20 = 0.f, mem21 = 0.f, mem22 = 0.f;
    float spk20 = 0.f, spk21 = 0.f, spk22 = 0.f;

    const ull BETA2 = pk2(0.92f, 0.92f);
    const ull NEG1  = pk2(-1.0f, -1.0f);

    const size_t xstride = (size_t)BATCH * NIN;
    const size_t ostride = (size_t)BATCH * NO;
    const float* xp = x + (size_t)b * NIN;
    float* outspk = out + (size_t)b * NO;
    float* outmem = out + (size_t)T_STEPS * BATCH * NO + (size_t)b * NO;

    float xc[NIN];
#pragma unroll
    for (int i = 0; i < NIN; i++) xc[i] = xp[i];

    for (int t = 0; t < T_STEPS; t++) {
        // prefetch x(t+1)
        float xn[NIN];
        const bool pf = (t + 1 < T_STEPS);
        const float* xpn = xp + xstride;
#pragma unroll
        for (int i = 0; i < NIN; i++) xn[i] = pf ? xpn[i] : 0.0f;

        // layer 1: mem1 = 0.92*mem1 + (b1 - spk1_prev) + x @ W1^T
#pragma unroll
        for (int j = 0; j < JP; j++)
            m1[j] = ffma2(m1[j], BETA2, ffma2(s1[j], NEG1, b1p[j]));

#pragma unroll
        for (int i = 0; i < NIN; i++) {
            const ull xx = pk2(xc[i], xc[i]);
            const ulonglong2 p0 = w1l[i][0];
            const ulonglong2 p1 = w1l[i][1];
            const ulonglong2 p2 = w1l[i][2];
            m1[0] = ffma2(xx, p0.x, m1[0]);
            m1[1] = ffma2(xx, p0.y, m1[1]);
            m1[2] = ffma2(xx, p1.x, m1[2]);
            m1[3] = ffma2(xx, p1.y, m1[3]);
            m1[4] = ffma2(xx, p2.x, m1[4]);
            m1[5] = ffma2(xx, p2.y, m1[5]);
        }
        // spike1 = (mem1 > 1)
#pragma unroll
        for (int j = 0; j < JP; j++) {
            float2 v = upk2(m1[j]);
            s1[j] = pk2(fsetgt(v.x, 1.0f), fsetgt(v.y, 1.0f));
        }

        // layer 2 partials
        ull a0 = 0ull, a1 = 0ull, a2 = 0ull;
        {
            const ulonglong2 q00 = w2l0[0], q01 = w2l0[1], q02 = w2l0[2];
            const ulonglong2 q10 = w2l1[0], q11 = w2l1[1], q12 = w2l1[2];
            const ulonglong2 q20 = w2l2[0], q21 = w2l2[1], q22 = w2l2[2];
            a0 = ffma2(s1[0], q00.x, a0); a0 = ffma2(s1[1], q00.y, a0);
            a0 = ffma2(s1[2], q01.x, a0); a0 = ffma2(s1[3], q01.y, a0);
            a0 = ffma2(s1[4], q02.x, a0); a0 = ffma2(s1[5], q02.y, a0);
            a1 = ffma2(s1[0], q10.x, a1); a1 = ffma2(s1[1], q10.y, a1);
            a1 = ffma2(s1[2], q11.x, a1); a1 = ffma2(s1[3], q11.y, a1);
            a1 = ffma2(s1[4], q12.x, a1); a1 = ffma2(s1[5], q12.y, a1);
            a2 = ffma2(s1[0], q20.x, a2); a2 = ffma2(s1[1], q20.y, a2);
            a2 = ffma2(s1[2], q21.x, a2); a2 = ffma2(s1[3], q21.y, a2);
            a2 = ffma2(s1[4], q22.x, a2); a2 = ffma2(s1[5], q22.y, a2);
        }
        float2 v0 = upk2(a0), v1 = upk2(a1), v2 = upk2(a2);
        float c0 = v0.x + v0.y, c1 = v1.x + v1.y, c2 = v2.x + v2.y;
#pragma unroll
        for (int d = 1; d < GSZ; d <<= 1) {
            c0 += __shfl_xor_sync(0xffffffffu, c0, d);
            c1 += __shfl_xor_sync(0xffffffffu, c1, d);
            c2 += __shfl_xor_sync(0xffffffffu, c2, d);
        }

        // layer 2 membrane + spike (replicated per lane)
        mem20 = fmaf(mem20, 0.92f, c0 + fmaf(spk20, -1.0f, b20));
        mem21 = fmaf(mem21, 0.92f, c1 + fmaf(spk21, -1.0f, b21));
        mem22 = fmaf(mem22, 0.92f, c2 + fmaf(spk22, -1.0f, b22));
        spk20 = fsetgt(mem20, 1.0f);
        spk21 = fsetgt(mem21, 1.0f);
        spk22 = fsetgt(mem22, 1.0f);

        // outputs: lanes 0-2 -> spk2, lanes 4-6 -> mem2
        if (s < 3) {
            float v = (s == 0) ? spk20 : ((s == 1) ? spk21 : spk22);
            outspk[s] = v;
        } else if (s >= 4 && s < 7) {
            float v = (s == 4) ? mem20 : ((s == 5) ? mem21 : mem22);
            outmem[s - 4] = v;
        }

        xp += xstride;
        outspk += ostride;
        outmem += ostride;
#pragma unroll
        for (int i = 0; i < NIN; i++) xc[i] = xn[i];
    }
}

extern "C" void kernel_launch(void* const* d_in, const int* in_sizes, int n_in,
                              void* d_out, int out_size) {
    const float* x  = (const float*)d_in[0];
    const float* W1 = (const float*)d_in[1];
    const float* b1 = (const float*)d_in[2];
    const float* W2 = (const float*)d_in[3];
    const float* b2 = (const float*)d_in[4];
    float* out = (float*)d_out;

    const int threads = 256;
    const int total   = BATCH * GSZ;   // 65536 threads, 256 CTAs, 2 CTAs/SM
    snn_kernel<<<total / threads, threads>>>(x, W1, b1, W2, b2, out);
}